// round 1
// baseline (speedup 1.0000x reference)
#include <cuda_runtime.h>
#include <cuda_bf16.h>

// GCN 2-layer: out = Ahat * relu(Ahat * X * W1 + b1) * W2 + b2
// Ahat = D^{-1/2} (A + I) D^{-1/2}, deg over dst (incl. self loop)

#define NMAX   100000
#define EMAX   1600000
#define IN_CH  128
#define HID    64
#define OUTC   32

// scratch (static device globals; no runtime allocation)
__device__ int   g_deg[NMAX];
__device__ float g_dis[NMAX];
__device__ float g_h1 [NMAX * HID];   // x @ W1
__device__ float g_agg1[NMAX * HID];  // aggregated layer-1 (then relu'd on read)
__device__ float g_h2 [NMAX * OUTC];  // relu(agg1) @ W2

__device__ __forceinline__ void red_add_v4(float* addr, float4 v) {
    asm volatile("red.global.add.v4.f32 [%0], {%1,%2,%3,%4};"
                 :: "l"(addr), "f"(v.x), "f"(v.y), "f"(v.z), "f"(v.w)
                 : "memory");
}

// ---------------- degree / normalization ----------------

__global__ void k_deg_init(int n) {
    int i = blockIdx.x * blockDim.x + threadIdx.x;
    if (i < n) g_deg[i] = 1;               // self loop
}

__global__ void k_deg_count(const int* __restrict__ ei, int E) {
    int e = blockIdx.x * blockDim.x + threadIdx.x;
    if (e < E) atomicAdd(&g_deg[ei[E + e]], 1);   // dst = ei[1][e]
}

__global__ void k_dis(int n) {
    int i = blockIdx.x * blockDim.x + threadIdx.x;
    if (i < n) g_dis[i] = rsqrtf((float)g_deg[i]);
}

// ---------------- GEMM1: h1 = x @ W1  (N x 128 @ 128 x 64) ----------------
// 32 nodes per block, 256 threads. smem: W1 (32KB) + x tile (16KB, XOR-swizzled).

__global__ __launch_bounds__(256) void k_gemm1(const float* __restrict__ x,
                                               const float* __restrict__ W1,
                                               int n) {
    __shared__ float sW[IN_CH * HID];      // 8192 floats = 32KB
    __shared__ float sx[32 * IN_CH];       // 4096 floats = 16KB
    int tid = threadIdx.x;
    int base = blockIdx.x * 32;

    for (int i = tid; i < IN_CH * HID; i += 256) sW[i] = W1[i];
    for (int i = tid; i < 32 * IN_CH; i += 256) {
        int r = i >> 7, c = i & 127;
        int node = base + r;
        float v = (node < n) ? x[node * IN_CH + c] : 0.f;
        sx[r * IN_CH + (c ^ (r & 31))] = v;    // XOR swizzle -> conflict-free col reads
    }
    __syncthreads();

    int node_sub = tid & 31;      // warp spans 32 nodes
    int cg = tid >> 5;            // 8 channel-groups of 8
    float acc[8];
#pragma unroll
    for (int j = 0; j < 8; j++) acc[j] = 0.f;

    const float* xr = sx + node_sub * IN_CH;
#pragma unroll 4
    for (int k = 0; k < IN_CH; k++) {
        float xv = xr[k ^ node_sub];
        const float4* wr = reinterpret_cast<const float4*>(sW + k * HID + cg * 8);
        float4 w0 = wr[0], w1 = wr[1];
        acc[0] += xv * w0.x; acc[1] += xv * w0.y;
        acc[2] += xv * w0.z; acc[3] += xv * w0.w;
        acc[4] += xv * w1.x; acc[5] += xv * w1.y;
        acc[6] += xv * w1.z; acc[7] += xv * w1.w;
    }

    int node = base + node_sub;
    if (node < n) {
        float4* o = reinterpret_cast<float4*>(g_h1 + node * HID + cg * 8);
        o[0] = make_float4(acc[0], acc[1], acc[2], acc[3]);
        o[1] = make_float4(acc[4], acc[5], acc[6], acc[7]);
    }
}

// ---------------- layer-1 self-loop init + bias ----------------
// agg1[i] = h1[i] * dis[i]^2 + b1

__global__ void k_self1(const float* __restrict__ b1, int n) {
    int t = blockIdx.x * blockDim.x + threadIdx.x;
    if (t >= n * (HID / 4)) return;
    int i = t >> 4, q = t & 15;
    float ds = g_dis[i];
    float w = ds * ds;
    float4 v = reinterpret_cast<const float4*>(g_h1)[i * 16 + q];
    float4 b = reinterpret_cast<const float4*>(b1)[q];
    float4 r = make_float4(v.x * w + b.x, v.y * w + b.y, v.z * w + b.z, v.w * w + b.w);
    reinterpret_cast<float4*>(g_agg1)[i * 16 + q] = r;
}

// ---------------- layer-1 edge scatter ----------------
// agg1[dst] += h1[src] * dis[src]*dis[dst];  16 threads/edge, float4 red

__global__ void k_edge1(const int* __restrict__ ei, int E) {
    int t = blockIdx.x * blockDim.x + threadIdx.x;
    if (t >= E * 16) return;
    int e = t >> 4, q = t & 15;
    int s = ei[e];
    int d = ei[E + e];
    float w = g_dis[s] * g_dis[d];
    float4 v = reinterpret_cast<const float4*>(g_h1)[s * 16 + q];
    v.x *= w; v.y *= w; v.z *= w; v.w *= w;
    red_add_v4(g_agg1 + d * HID + q * 4, v);
}

// ---------------- GEMM2: h2 = relu(agg1) @ W2  (N x 64 @ 64 x 32) ----------
// 64 nodes per block, 256 threads. smem: W2 (8KB) + relu(agg1) tile (16KB).

__global__ __launch_bounds__(256) void k_gemm2(const float* __restrict__ W2, int n) {
    __shared__ float sW[HID * OUTC];       // 2048 floats = 8KB
    __shared__ float sx[64 * HID];         // 4096 floats = 16KB
    int tid = threadIdx.x;
    int base = blockIdx.x * 64;

    for (int i = tid; i < HID * OUTC; i += 256) sW[i] = W2[i];
    for (int i = tid; i < 64 * HID; i += 256) {
        int r = i >> 6, c = i & 63;
        int node = base + r;
        float v = (node < n) ? fmaxf(g_agg1[node * HID + c], 0.f) : 0.f;  // fused relu
        sx[r * HID + (c ^ (r & 31))] = v;
    }
    __syncthreads();

    int node_sub = tid & 63;
    int cg = tid >> 6;            // 4 channel-groups of 8
    float acc[8];
#pragma unroll
    for (int j = 0; j < 8; j++) acc[j] = 0.f;

    const float* xr = sx + node_sub * HID;
    int sw = node_sub & 31;
#pragma unroll 4
    for (int k = 0; k < HID; k++) {
        float xv = xr[k ^ sw];
        const float4* wr = reinterpret_cast<const float4*>(sW + k * OUTC + cg * 8);
        float4 w0 = wr[0], w1 = wr[1];
        acc[0] += xv * w0.x; acc[1] += xv * w0.y;
        acc[2] += xv * w0.z; acc[3] += xv * w0.w;
        acc[4] += xv * w1.x; acc[5] += xv * w1.y;
        acc[6] += xv * w1.z; acc[7] += xv * w1.w;
    }

    int node = base + node_sub;
    if (node < n) {
        float4* o = reinterpret_cast<float4*>(g_h2 + node * OUTC + cg * 8);
        o[0] = make_float4(acc[0], acc[1], acc[2], acc[3]);
        o[1] = make_float4(acc[4], acc[5], acc[6], acc[7]);
    }
}

// ---------------- layer-2 self-loop init + bias (writes d_out) ------------

__global__ void k_self2(const float* __restrict__ b2, float* __restrict__ out, int n) {
    int t = blockIdx.x * blockDim.x + threadIdx.x;
    if (t >= n * (OUTC / 4)) return;
    int i = t >> 3, q = t & 7;
    float ds = g_dis[i];
    float w = ds * ds;
    float4 v = reinterpret_cast<const float4*>(g_h2)[i * 8 + q];
    float4 b = reinterpret_cast<const float4*>(b2)[q];
    float4 r = make_float4(v.x * w + b.x, v.y * w + b.y, v.z * w + b.z, v.w * w + b.w);
    reinterpret_cast<float4*>(out)[i * 8 + q] = r;
}

// ---------------- layer-2 edge scatter (into d_out) ----------------------

__global__ void k_edge2(const int* __restrict__ ei, float* __restrict__ out, int E) {
    int t = blockIdx.x * blockDim.x + threadIdx.x;
    if (t >= E * 8) return;
    int e = t >> 3, q = t & 7;
    int s = ei[e];
    int d = ei[E + e];
    float w = g_dis[s] * g_dis[d];
    float4 v = reinterpret_cast<const float4*>(g_h2)[s * 8 + q];
    v.x *= w; v.y *= w; v.z *= w; v.w *= w;
    red_add_v4(out + d * OUTC + q * 4, v);
}

// ---------------- launch ----------------

extern "C" void kernel_launch(void* const* d_in, const int* in_sizes, int n_in,
                              void* d_out, int out_size) {
    const float* x  = (const float*)d_in[0];
    const int*   ei = (const int*)  d_in[1];
    const float* W1 = (const float*)d_in[2];
    const float* b1 = (const float*)d_in[3];
    const float* W2 = (const float*)d_in[4];
    const float* b2 = (const float*)d_in[5];
    float* out = (float*)d_out;

    int N = in_sizes[0] / IN_CH;
    int E = in_sizes[1] / 2;

    const int T = 256;
    k_deg_init <<<(N + T - 1) / T, T>>>(N);
    k_deg_count<<<(E + T - 1) / T, T>>>(ei, E);
    k_dis      <<<(N + T - 1) / T, T>>>(N);

    k_gemm1<<<(N + 31) / 32, 256>>>(x, W1, N);
    k_self1<<<(N * 16 + T - 1) / T, T>>>(b1, N);
    k_edge1<<<(E * 16 + T - 1) / T, T>>>(ei, E);

    k_gemm2<<<(N + 63) / 64, 256>>>(W2, N);
    k_self2<<<(N * 8 + T - 1) / T, T>>>(b2, out, N);
    k_edge2<<<(E * 8 + T - 1) / T, T>>>(ei, out, E);
}

// round 2
// speedup vs baseline: 1.2344x; 1.2344x over previous
#include <cuda_runtime.h>
#include <cuda_bf16.h>

// GCN 2-layer: out = Ahat * relu(Ahat * X * W1 + b1) * W2 + b2
// Ahat = D^{-1/2} (A + I) D^{-1/2}

#define NMAX   100000
#define EMAX   1600000
#define IN_CH  128
#define HID    64
#define OUTC   32

__device__ int   g_deg[NMAX];
__device__ float g_dis[NMAX];
__device__ float g_h1 [NMAX * HID];   // x @ W1
__device__ float g_agg1[NMAX * HID];  // dis^2*h1 + b1, then += edge msgs
__device__ float g_h2 [NMAX * OUTC];  // relu(agg1) @ W2

__device__ __forceinline__ void red_add_v4(float* addr, float4 v) {
    asm volatile("red.global.add.v4.f32 [%0], {%1,%2,%3,%4};"
                 :: "l"(addr), "f"(v.x), "f"(v.y), "f"(v.z), "f"(v.w)
                 : "memory");
}

// ---------------- degree / normalization ----------------

__global__ void k_deg_init(int n) {
    int i = blockIdx.x * blockDim.x + threadIdx.x;
    if (i < n) g_deg[i] = 1;               // self loop
}

__global__ void k_deg_count(const int* __restrict__ ei, int E) {
    int e = blockIdx.x * blockDim.x + threadIdx.x;
    if (e < E) atomicAdd(&g_deg[ei[E + e]], 1);
}

__global__ void k_dis(int n) {
    int i = blockIdx.x * blockDim.x + threadIdx.x;
    if (i < n) g_dis[i] = rsqrtf((float)g_deg[i]);
}

// ---------------- GEMM1: h1 = x @ W1, agg1 = dis^2*h1 + b1 --------------
// Tile: 128 nodes x 64 ch per block, 256 threads, 4 nodes x 8 ch per thread.
// K chunked by 32. sx stored k-major [k][node], row stride 129 (conflict-free).

#define KC1 32

__global__ __launch_bounds__(256) void k_gemm1(const float* __restrict__ x,
                                               const float* __restrict__ W1,
                                               const float* __restrict__ b1,
                                               int n) {
    __shared__ float sx[KC1 * 129];        // 16.5 KB
    __shared__ float sW[KC1 * HID];        // 8 KB

    int tid = threadIdx.x;
    int base = blockIdx.x * 128;
    int ng = tid & 31;                     // nodes: ng + 32*i
    int cg = tid >> 5;                     // ch: 8*cg .. 8*cg+7

    float acc[4][8];
#pragma unroll
    for (int i = 0; i < 4; i++)
#pragma unroll
        for (int j = 0; j < 8; j++) acc[i][j] = 0.f;

    for (int kc = 0; kc < IN_CH; kc += KC1) {
        __syncthreads();
        // load W chunk: KC1 x 64 = 2048 floats
#pragma unroll
        for (int i = 0; i < (KC1 * HID) / 256; i++) {
            int idx = tid + 256 * i;
            sW[idx] = W1[(kc + (idx >> 6)) * HID + (idx & 63)];
        }
        // load x chunk transposed: 128 nodes x KC1, float4 per thread x4
#pragma unroll
        for (int i = 0; i < 4; i++) {
            int f = tid + 256 * i;         // 0..1023
            int node = f >> 3;             // 0..127
            int qq = f & 7;                // k = 4*qq
            int gn = base + node;
            float4 v = make_float4(0.f, 0.f, 0.f, 0.f);
            if (gn < n) v = reinterpret_cast<const float4*>(x + gn * IN_CH + kc)[qq];
            int k0 = 4 * qq;
            sx[(k0 + 0) * 129 + node] = v.x;
            sx[(k0 + 1) * 129 + node] = v.y;
            sx[(k0 + 2) * 129 + node] = v.z;
            sx[(k0 + 3) * 129 + node] = v.w;
        }
        __syncthreads();

#pragma unroll
        for (int k = 0; k < KC1; k++) {
            float xv0 = sx[k * 129 + ng];
            float xv1 = sx[k * 129 + ng + 32];
            float xv2 = sx[k * 129 + ng + 64];
            float xv3 = sx[k * 129 + ng + 96];
            const float4* wr = reinterpret_cast<const float4*>(sW + k * HID + cg * 8);
            float4 w0 = wr[0], w1 = wr[1];
            float w[8] = {w0.x, w0.y, w0.z, w0.w, w1.x, w1.y, w1.z, w1.w};
#pragma unroll
            for (int j = 0; j < 8; j++) {
                acc[0][j] += xv0 * w[j];
                acc[1][j] += xv1 * w[j];
                acc[2][j] += xv2 * w[j];
                acc[3][j] += xv3 * w[j];
            }
        }
    }

    float4 bb0 = reinterpret_cast<const float4*>(b1 + cg * 8)[0];
    float4 bb1 = reinterpret_cast<const float4*>(b1 + cg * 8)[1];
#pragma unroll
    for (int i = 0; i < 4; i++) {
        int node = base + ng + 32 * i;
        if (node >= n) continue;
        float ds = g_dis[node];
        float w = ds * ds;
        float4* oh = reinterpret_cast<float4*>(g_h1 + node * HID + cg * 8);
        float4* oa = reinterpret_cast<float4*>(g_agg1 + node * HID + cg * 8);
        float4 a0 = make_float4(acc[i][0], acc[i][1], acc[i][2], acc[i][3]);
        float4 a1 = make_float4(acc[i][4], acc[i][5], acc[i][6], acc[i][7]);
        oh[0] = a0; oh[1] = a1;
        oa[0] = make_float4(a0.x * w + bb0.x, a0.y * w + bb0.y,
                            a0.z * w + bb0.z, a0.w * w + bb0.w);
        oa[1] = make_float4(a1.x * w + bb1.x, a1.y * w + bb1.y,
                            a1.z * w + bb1.z, a1.w * w + bb1.w);
    }
}

// ---------------- layer-1 edge scatter ----------------

__global__ void k_edge1(const int* __restrict__ ei, int E) {
    int t = blockIdx.x * blockDim.x + threadIdx.x;
    if (t >= E * 16) return;
    int e = t >> 4, q = t & 15;
    int s = ei[e];
    int d = ei[E + e];
    float w = g_dis[s] * g_dis[d];
    float4 v = reinterpret_cast<const float4*>(g_h1)[s * 16 + q];
    v.x *= w; v.y *= w; v.z *= w; v.w *= w;
    red_add_v4(g_agg1 + d * HID + q * 4, v);
}

// ---------------- GEMM2: h2 = relu(agg1) @ W2, out = dis^2*h2 + b2 ------
// Tile: 128 nodes x 32 ch per block, 256 threads, 2 nodes x 8 ch per thread.

__global__ __launch_bounds__(256) void k_gemm2(const float* __restrict__ W2,
                                               const float* __restrict__ b2,
                                               float* __restrict__ out, int n) {
    __shared__ float sx[HID * 129];        // 33 KB
    __shared__ float sW[HID * OUTC];       // 8 KB

    int tid = threadIdx.x;
    int base = blockIdx.x * 128;
    int ng = tid & 63;                     // nodes: ng, ng+64
    int cg = tid >> 6;                     // ch: 8*cg .. 8*cg+7

    // load W2
#pragma unroll
    for (int i = 0; i < (HID * OUTC) / 256; i++) sW[tid + 256 * i] = W2[tid + 256 * i];

    // load relu(agg1) tile transposed: 128 nodes x 64 k
#pragma unroll
    for (int i = 0; i < 8; i++) {
        int f = tid + 256 * i;             // 0..2047
        int node = f >> 4;                 // 0..127
        int qq = f & 15;                   // k = 4*qq
        int gn = base + node;
        float4 v = make_float4(0.f, 0.f, 0.f, 0.f);
        if (gn < n) {
            v = reinterpret_cast<const float4*>(g_agg1 + gn * HID)[qq];
            v.x = fmaxf(v.x, 0.f); v.y = fmaxf(v.y, 0.f);
            v.z = fmaxf(v.z, 0.f); v.w = fmaxf(v.w, 0.f);
        }
        int k0 = 4 * qq;
        sx[(k0 + 0) * 129 + node] = v.x;
        sx[(k0 + 1) * 129 + node] = v.y;
        sx[(k0 + 2) * 129 + node] = v.z;
        sx[(k0 + 3) * 129 + node] = v.w;
    }
    __syncthreads();

    float acc[2][8];
#pragma unroll
    for (int i = 0; i < 2; i++)
#pragma unroll
        for (int j = 0; j < 8; j++) acc[i][j] = 0.f;

#pragma unroll
    for (int k = 0; k < HID; k++) {
        float xv0 = sx[k * 129 + ng];
        float xv1 = sx[k * 129 + ng + 64];
        const float4* wr = reinterpret_cast<const float4*>(sW + k * OUTC + cg * 8);
        float4 w0 = wr[0], w1 = wr[1];
        float w[8] = {w0.x, w0.y, w0.z, w0.w, w1.x, w1.y, w1.z, w1.w};
#pragma unroll
        for (int j = 0; j < 8; j++) {
            acc[0][j] += xv0 * w[j];
            acc[1][j] += xv1 * w[j];
        }
    }

    float4 bb0 = reinterpret_cast<const float4*>(b2 + cg * 8)[0];
    float4 bb1 = reinterpret_cast<const float4*>(b2 + cg * 8)[1];
#pragma unroll
    for (int i = 0; i < 2; i++) {
        int node = base + ng + 64 * i;
        if (node >= n) continue;
        float ds = g_dis[node];
        float w = ds * ds;
        float4* oh = reinterpret_cast<float4*>(g_h2 + node * OUTC + cg * 8);
        float4* oo = reinterpret_cast<float4*>(out + node * OUTC + cg * 8);
        float4 a0 = make_float4(acc[i][0], acc[i][1], acc[i][2], acc[i][3]);
        float4 a1 = make_float4(acc[i][4], acc[i][5], acc[i][6], acc[i][7]);
        oh[0] = a0; oh[1] = a1;
        oo[0] = make_float4(a0.x * w + bb0.x, a0.y * w + bb0.y,
                            a0.z * w + bb0.z, a0.w * w + bb0.w);
        oo[1] = make_float4(a1.x * w + bb1.x, a1.y * w + bb1.y,
                            a1.z * w + bb1.z, a1.w * w + bb1.w);
    }
}

// ---------------- layer-2 edge scatter (into d_out) ----------------------

__global__ void k_edge2(const int* __restrict__ ei, float* __restrict__ out, int E) {
    int t = blockIdx.x * blockDim.x + threadIdx.x;
    if (t >= E * 8) return;
    int e = t >> 3, q = t & 7;
    int s = ei[e];
    int d = ei[E + e];
    float w = g_dis[s] * g_dis[d];
    float4 v = reinterpret_cast<const float4*>(g_h2)[s * 8 + q];
    v.x *= w; v.y *= w; v.z *= w; v.w *= w;
    red_add_v4(out + d * OUTC + q * 4, v);
}

// ---------------- launch ----------------

extern "C" void kernel_launch(void* const* d_in, const int* in_sizes, int n_in,
                              void* d_out, int out_size) {
    const float* x  = (const float*)d_in[0];
    const int*   ei = (const int*)  d_in[1];
    const float* W1 = (const float*)d_in[2];
    const float* b1 = (const float*)d_in[3];
    const float* W2 = (const float*)d_in[4];
    const float* b2 = (const float*)d_in[5];
    float* out = (float*)d_out;

    int N = in_sizes[0] / IN_CH;
    int E = in_sizes[1] / 2;

    const int T = 256;
    k_deg_init <<<(N + T - 1) / T, T>>>(N);
    k_deg_count<<<(E + T - 1) / T, T>>>(ei, E);
    k_dis      <<<(N + T - 1) / T, T>>>(N);

    k_gemm1<<<(N + 127) / 128, 256>>>(x, W1, b1, N);
    k_edge1<<<(E * 16 + T - 1) / T, T>>>(ei, E);

    k_gemm2<<<(N + 127) / 128, 256>>>(W2, b2, out, N);
    k_edge2<<<(E * 8 + T - 1) / T, T>>>(ei, out, E);
}

// round 3
// speedup vs baseline: 1.2960x; 1.0499x over previous
#include <cuda_runtime.h>
#include <cuda_bf16.h>

// GCN 2-layer: out = Ahat * relu(Ahat * X * W1 + b1) * W2 + b2
// Ahat = D^{-1/2} (A + I) D^{-1/2}

#define NMAX   100000
#define EMAX   1600000
#define IN_CH  128
#define HID    64
#define OUTC   32

typedef unsigned long long ull;

__device__ int   g_deg[NMAX];
__device__ float g_dis[NMAX];
__device__ float g_h1 [NMAX * HID];   // x @ W1
__device__ float g_agg1[NMAX * HID];  // dis^2*h1 + b1, then += edge msgs
__device__ float g_h2 [NMAX * OUTC];  // relu(agg1) @ W2

__device__ __forceinline__ void red_add_v4(float* addr, float4 v) {
    asm volatile("red.global.add.v4.f32 [%0], {%1,%2,%3,%4};"
                 :: "l"(addr), "f"(v.x), "f"(v.y), "f"(v.z), "f"(v.w)
                 : "memory");
}

// packed dual-fp32 FMA: acc.{lo,hi} += a.{lo,hi} * b.{lo,hi}
__device__ __forceinline__ void fma2(ull& acc, ull a, ull b) {
    asm("fma.rn.f32x2 %0, %1, %2, %0;" : "+l"(acc) : "l"(a), "l"(b));
}

__device__ __forceinline__ float unpack_sum(ull v) {
    float2 f;
    asm("mov.b64 {%0, %1}, %2;" : "=f"(f.x), "=f"(f.y) : "l"(v));
    return f.x + f.y;
}

// ---------------- degree / normalization ----------------

__global__ void k_deg_init(int n) {
    int i = blockIdx.x * blockDim.x + threadIdx.x;
    if (i < n) g_deg[i] = 1;               // self loop
}

__global__ void k_deg_count(const int* __restrict__ ei, int E) {
    int e = blockIdx.x * blockDim.x + threadIdx.x;
    if (e < E) atomicAdd(&g_deg[ei[E + e]], 1);
}

__global__ void k_dis(int n) {
    int i = blockIdx.x * blockDim.x + threadIdx.x;
    if (i < n) g_dis[i] = rsqrtf((float)g_deg[i]);
}

// ---------------- GEMM1: h1 = x @ W1, agg1 = dis^2*h1 + b1 --------------
// Tile: 64 nodes x 64 ch / block, 256 thr, 2 nodes x 8 ch per thread.
// K chunked by 64; K paired into f32x2 (even/odd partial sums).
// sx node-major stride 66 (LDS.64 reads bank = 2l+2k2: conflict-free).
// sWp: k-pair interleaved [k2][ch] as float2; warp-broadcast LDS.128.

#define KC 64

__global__ __launch_bounds__(256) void k_gemm1(const float* __restrict__ x,
                                               const float* __restrict__ W1,
                                               const float* __restrict__ b1,
                                               int n) {
    __shared__ float sx[64 * 66];            // 16.5 KB
    __shared__ float sWp[(KC / 2) * 128];    // 32 k2 x 64 ch x 2 = 16 KB

    int tid = threadIdx.x;
    int base = blockIdx.x * 64;
    int ng = tid & 31;                       // nodes ng, ng+32
    int cg = tid >> 5;                       // ch 8*cg .. 8*cg+7

    ull acc[2][8];
#pragma unroll
    for (int i = 0; i < 2; i++)
#pragma unroll
        for (int j = 0; j < 8; j++) acc[i][j] = 0ull;

    for (int kc = 0; kc < IN_CH; kc += KC) {
        __syncthreads();
        // W chunk, interleaved by k-pairs: 4096 floats
#pragma unroll
        for (int i = 0; i < 16; i++) {
            int idx = tid + 256 * i;
            int k = idx >> 6, c = idx & 63;
            sWp[(k >> 1) * 128 + c * 2 + (k & 1)] = W1[(kc + k) * HID + c];
        }
        // x chunk: 64 nodes x 64 k
#pragma unroll
        for (int i = 0; i < 4; i++) {
            int f = tid + 256 * i;           // 0..1023
            int node = f >> 4;               // 16 float4 per node row
            int q = f & 15;
            int gn = base + node;
            float4 v = make_float4(0.f, 0.f, 0.f, 0.f);
            if (gn < n) v = reinterpret_cast<const float4*>(x + gn * IN_CH + kc)[q];
            float* r = sx + node * 66 + 4 * q;
            r[0] = v.x; r[1] = v.y; r[2] = v.z; r[3] = v.w;
        }
        __syncthreads();

#pragma unroll
        for (int k2 = 0; k2 < KC / 2; k2++) {
            ull xv0 = *reinterpret_cast<const ull*>(sx + ng * 66 + 2 * k2);
            ull xv1 = *reinterpret_cast<const ull*>(sx + (ng + 32) * 66 + 2 * k2);
            const ulonglong2* wr =
                reinterpret_cast<const ulonglong2*>(sWp + k2 * 128 + cg * 16);
            ulonglong2 wa = wr[0], wb = wr[1], wc = wr[2], wd = wr[3];
            fma2(acc[0][0], xv0, wa.x); fma2(acc[1][0], xv1, wa.x);
            fma2(acc[0][1], xv0, wa.y); fma2(acc[1][1], xv1, wa.y);
            fma2(acc[0][2], xv0, wb.x); fma2(acc[1][2], xv1, wb.x);
            fma2(acc[0][3], xv0, wb.y); fma2(acc[1][3], xv1, wb.y);
            fma2(acc[0][4], xv0, wc.x); fma2(acc[1][4], xv1, wc.x);
            fma2(acc[0][5], xv0, wc.y); fma2(acc[1][5], xv1, wc.y);
            fma2(acc[0][6], xv0, wd.x); fma2(acc[1][6], xv1, wd.x);
            fma2(acc[0][7], xv0, wd.y); fma2(acc[1][7], xv1, wd.y);
        }
    }

    float4 bb0 = reinterpret_cast<const float4*>(b1 + cg * 8)[0];
    float4 bb1 = reinterpret_cast<const float4*>(b1 + cg * 8)[1];
#pragma unroll
    for (int i = 0; i < 2; i++) {
        int node = base + ng + 32 * i;
        if (node >= n) continue;
        float ds = g_dis[node];
        float w = ds * ds;
        float r0 = unpack_sum(acc[i][0]), r1 = unpack_sum(acc[i][1]);
        float r2 = unpack_sum(acc[i][2]), r3 = unpack_sum(acc[i][3]);
        float r4 = unpack_sum(acc[i][4]), r5 = unpack_sum(acc[i][5]);
        float r6 = unpack_sum(acc[i][6]), r7 = unpack_sum(acc[i][7]);
        float4* oh = reinterpret_cast<float4*>(g_h1 + node * HID + cg * 8);
        float4* oa = reinterpret_cast<float4*>(g_agg1 + node * HID + cg * 8);
        oh[0] = make_float4(r0, r1, r2, r3);
        oh[1] = make_float4(r4, r5, r6, r7);
        oa[0] = make_float4(r0 * w + bb0.x, r1 * w + bb0.y,
                            r2 * w + bb0.z, r3 * w + bb0.w);
        oa[1] = make_float4(r4 * w + bb1.x, r5 * w + bb1.y,
                            r6 * w + bb1.z, r7 * w + bb1.w);
    }
}

// ---------------- layer-1 edge scatter ----------------

__global__ void k_edge1(const int* __restrict__ ei, int E) {
    int t = blockIdx.x * blockDim.x + threadIdx.x;
    if (t >= E * 16) return;
    int e = t >> 4, q = t & 15;
    int s = ei[e];
    int d = ei[E + e];
    float w = g_dis[s] * g_dis[d];
    float4 v = reinterpret_cast<const float4*>(g_h1)[s * 16 + q];
    v.x *= w; v.y *= w; v.z *= w; v.w *= w;
    red_add_v4(g_agg1 + d * HID + q * 4, v);
}

// ---------------- GEMM2: h2 = relu(agg1) @ W2, out = dis^2*h2 + b2 ------
// Tile: 128 nodes x 32 ch / block, 256 thr, 4 nodes x 4 ch per thread.
// Same f32x2 K-pairing; relu fused into the smem stage.

__global__ __launch_bounds__(256) void k_gemm2(const float* __restrict__ W2,
                                               const float* __restrict__ b2,
                                               float* __restrict__ out, int n) {
    __shared__ float sx[128 * 66];           // 33 KB
    __shared__ float sWp[(HID / 2) * 64];    // 32 k2 x 32 ch x 2 = 8 KB

    int tid = threadIdx.x;
    int base = blockIdx.x * 128;
    int ng = tid & 31;                       // nodes ng + 32*i
    int cg = tid >> 5;                       // ch 4*cg .. 4*cg+3

    // W2 interleaved by k-pairs: 2048 floats
#pragma unroll
    for (int i = 0; i < 8; i++) {
        int idx = tid + 256 * i;
        int k = idx >> 5, c = idx & 31;
        sWp[(k >> 1) * 64 + c * 2 + (k & 1)] = W2[k * OUTC + c];
    }
    // relu(agg1) tile: 128 nodes x 64 k
#pragma unroll
    for (int i = 0; i < 8; i++) {
        int f = tid + 256 * i;               // 0..2047
        int node = f >> 4;
        int q = f & 15;
        int gn = base + node;
        float4 v = make_float4(0.f, 0.f, 0.f, 0.f);
        if (gn < n) {
            v = reinterpret_cast<const float4*>(g_agg1 + gn * HID)[q];
            v.x = fmaxf(v.x, 0.f); v.y = fmaxf(v.y, 0.f);
            v.z = fmaxf(v.z, 0.f); v.w = fmaxf(v.w, 0.f);
        }
        float* r = sx + node * 66 + 4 * q;
        r[0] = v.x; r[1] = v.y; r[2] = v.z; r[3] = v.w;
    }
    __syncthreads();

    ull acc[4][4];
#pragma unroll
    for (int i = 0; i < 4; i++)
#pragma unroll
        for (int j = 0; j < 4; j++) acc[i][j] = 0ull;

#pragma unroll
    for (int k2 = 0; k2 < HID / 2; k2++) {
        ull xv0 = *reinterpret_cast<const ull*>(sx + ng * 66 + 2 * k2);
        ull xv1 = *reinterpret_cast<const ull*>(sx + (ng + 32) * 66 + 2 * k2);
        ull xv2 = *reinterpret_cast<const ull*>(sx + (ng + 64) * 66 + 2 * k2);
        ull xv3 = *reinterpret_cast<const ull*>(sx + (ng + 96) * 66 + 2 * k2);
        const ulonglong2* wr =
            reinterpret_cast<const ulonglong2*>(sWp + k2 * 64 + cg * 8);
        ulonglong2 wa = wr[0], wb = wr[1];
        fma2(acc[0][0], xv0, wa.x); fma2(acc[1][0], xv1, wa.x);
        fma2(acc[2][0], xv2, wa.x); fma2(acc[3][0], xv3, wa.x);
        fma2(acc[0][1], xv0, wa.y); fma2(acc[1][1], xv1, wa.y);
        fma2(acc[2][1], xv2, wa.y); fma2(acc[3][1], xv3, wa.y);
        fma2(acc[0][2], xv0, wb.x); fma2(acc[1][2], xv1, wb.x);
        fma2(acc[2][2], xv2, wb.x); fma2(acc[3][2], xv3, wb.x);
        fma2(acc[0][3], xv0, wb.y); fma2(acc[1][3], xv1, wb.y);
        fma2(acc[2][3], xv2, wb.y); fma2(acc[3][3], xv3, wb.y);
    }

    float4 bb = reinterpret_cast<const float4*>(b2 + cg * 4)[0];
#pragma unroll
    for (int i = 0; i < 4; i++) {
        int node = base + ng + 32 * i;
        if (node >= n) continue;
        float ds = g_dis[node];
        float w = ds * ds;
        float r0 = unpack_sum(acc[i][0]), r1 = unpack_sum(acc[i][1]);
        float r2 = unpack_sum(acc[i][2]), r3 = unpack_sum(acc[i][3]);
        float4* oh = reinterpret_cast<float4*>(g_h2 + node * OUTC + cg * 4);
        float4* oo = reinterpret_cast<float4*>(out + node * OUTC + cg * 4);
        oh[0] = make_float4(r0, r1, r2, r3);
        oo[0] = make_float4(r0 * w + bb.x, r1 * w + bb.y,
                            r2 * w + bb.z, r3 * w + bb.w);
    }
}

// ---------------- layer-2 edge scatter (into d_out) ----------------------

__global__ void k_edge2(const int* __restrict__ ei, float* __restrict__ out, int E) {
    int t = blockIdx.x * blockDim.x + threadIdx.x;
    if (t >= E * 8) return;
    int e = t >> 3, q = t & 7;
    int s = ei[e];
    int d = ei[E + e];
    float w = g_dis[s] * g_dis[d];
    float4 v = reinterpret_cast<const float4*>(g_h2)[s * 8 + q];
    v.x *= w; v.y *= w; v.z *= w; v.w *= w;
    red_add_v4(out + d * OUTC + q * 4, v);
}

// ---------------- launch ----------------

extern "C" void kernel_launch(void* const* d_in, const int* in_sizes, int n_in,
                              void* d_out, int out_size) {
    const float* x  = (const float*)d_in[0];
    const int*   ei = (const int*)  d_in[1];
    const float* W1 = (const float*)d_in[2];
    const float* b1 = (const float*)d_in[3];
    const float* W2 = (const float*)d_in[4];
    const float* b2 = (const float*)d_in[5];
    float* out = (float*)d_out;

    int N = in_sizes[0] / IN_CH;
    int E = in_sizes[1] / 2;

    const int T = 256;
    k_deg_init <<<(N + T - 1) / T, T>>>(N);
    k_deg_count<<<(E + T - 1) / T, T>>>(ei, E);
    k_dis      <<<(N + T - 1) / T, T>>>(N);

    k_gemm1<<<(N + 63) / 64, 256>>>(x, W1, b1, N);
    k_edge1<<<(E * 16 + T - 1) / T, T>>>(ei, E);

    k_gemm2<<<(N + 127) / 128, 256>>>(W2, b2, out, N);
    k_edge2<<<(E * 8 + T - 1) / T, T>>>(ei, out, E);
}